// round 7
// baseline (speedup 1.0000x reference)
#include <cuda_runtime.h>
#include <cuda_bf16.h>
#include <cstdint>
#include <cstddef>

#define N_TOK 8192
#define G_DIM 2048
#define D_DIM 64

// ---------------- scratch (static device allocations are allowed) ----------
__device__ float         g_S   [(size_t)N_TOK * N_TOK];   // 256 MB scores
__device__ __nv_bfloat16 g_Phi [(size_t)N_TOK * N_TOK];   // 128 MB
__device__ __nv_bfloat16 g_Plo [(size_t)N_TOK * N_TOK];   // 128 MB
__device__ __nv_bfloat16 g_EhiT[(size_t)G_DIM * N_TOK];   //  32 MB (transposed)
__device__ __nv_bfloat16 g_EloT[(size_t)G_DIM * N_TOK];   //  32 MB
__device__ float         g_norm[N_TOK];

// ---------------- PTX helpers (NO tcgen05 — sm_103 plain target) -----------
__device__ __forceinline__ uint32_t smem_u32(const void* p) {
    uint32_t r;
    asm("{ .reg .u64 t; cvta.to.shared.u64 t, %1; cvt.u32.u64 %0, t; }"
        : "=r"(r) : "l"(p));
    return r;
}

__device__ __forceinline__ void cp16(uint32_t dst, const void* src) {
    asm volatile("cp.async.cg.shared.global [%0], [%1], 16;" :: "r"(dst), "l"(src));
}
#define CP_COMMIT() asm volatile("cp.async.commit_group;" ::: "memory")
#define CP_WAIT(n)  asm volatile("cp.async.wait_group %0;" :: "n"(n) : "memory")

__device__ __forceinline__ void ldsm4(uint32_t* r, uint32_t addr) {
    asm volatile("ldmatrix.sync.aligned.m8n8.x4.shared.b16 {%0,%1,%2,%3}, [%4];"
                 : "=r"(r[0]), "=r"(r[1]), "=r"(r[2]), "=r"(r[3]) : "r"(addr));
}

__device__ __forceinline__ void mma16816(float* c, const uint32_t* a, const uint32_t* b) {
    asm volatile(
        "mma.sync.aligned.m16n8k16.row.col.f32.bf16.bf16.f32 "
        "{%0,%1,%2,%3}, {%4,%5,%6,%7}, {%8,%9}, {%0,%1,%2,%3};"
        : "+f"(c[0]), "+f"(c[1]), "+f"(c[2]), "+f"(c[3])
        : "r"(a[0]), "r"(a[1]), "r"(a[2]), "r"(a[3]), "r"(b[0]), "r"(b[1]));
}

// ---------------- K1: row norms of encoding --------------------------------
__global__ void k_norm(const float* __restrict__ enc) {
    int j = blockIdx.x * 256 + threadIdx.x;
    const float4* p = reinterpret_cast<const float4*>(enc + (size_t)j * D_DIM);
    float s = 0.f;
#pragma unroll
    for (int k = 0; k < 16; k++) {
        float4 v = p[k];
        s += v.x * v.x + v.y * v.y + v.z * v.z + v.w * v.w;
    }
    g_norm[j] = s;
}

// ---------------- K2: transpose + bf16 split of expression -----------------
// expression [8192, 2048] f32 -> E_hi^T, E_lo^T [2048, 8192] bf16
__global__ void k_esplit(const float* __restrict__ expr) {
    __shared__ float tile[32][33];
    int g0 = blockIdx.x * 32, j0 = blockIdx.y * 32;
    int tx = threadIdx.x, ty = threadIdx.y;  // 32 x 8
#pragma unroll
    for (int i = 0; i < 32; i += 8)
        tile[ty + i][tx] = expr[(size_t)(j0 + ty + i) * G_DIM + g0 + tx];
    __syncthreads();
#pragma unroll
    for (int i = 0; i < 32; i += 8) {
        int g = g0 + ty + i, j = j0 + tx;
        float v = tile[tx][ty + i];
        __nv_bfloat16 h = __float2bfloat16(v);
        float r = v - __bfloat162float(h);
        g_EhiT[(size_t)g * N_TOK + j] = h;
        g_EloT[(size_t)g * N_TOK + j] = __float2bfloat16(r);
    }
}

// ---------------- K3: score matrix S = -dist + q_j -------------------------
#define SC_PITCH 129
__global__ __launch_bounds__(256) void k_score(const float* __restrict__ enc,
                                               const float* __restrict__ qual) {
    extern __shared__ char dyn_smem[];
    float* sA = reinterpret_cast<float*>(dyn_smem);            // [64][129] d-major (i-tile)
    float* sB = sA + 64 * SC_PITCH;                            // [64][129] d-major (j-tile)
    int t = threadIdx.x;
    int j0 = blockIdx.x * 128, i0 = blockIdx.y * 128;

#pragma unroll
    for (int k = 0; k < 8; k++) {
        int f = k * 256 + t;            // float4 index, 0..2047
        int row = f >> 4, dq = f & 15;
        float4 va = *reinterpret_cast<const float4*>(enc + (size_t)(i0 + row) * D_DIM + dq * 4);
        float4 vb = *reinterpret_cast<const float4*>(enc + (size_t)(j0 + row) * D_DIM + dq * 4);
        int d = dq * 4;
        sA[(d + 0) * SC_PITCH + row] = va.x;
        sA[(d + 1) * SC_PITCH + row] = va.y;
        sA[(d + 2) * SC_PITCH + row] = va.z;
        sA[(d + 3) * SC_PITCH + row] = va.w;
        sB[(d + 0) * SC_PITCH + row] = vb.x;
        sB[(d + 1) * SC_PITCH + row] = vb.y;
        sB[(d + 2) * SC_PITCH + row] = vb.z;
        sB[(d + 3) * SC_PITCH + row] = vb.w;
    }
    __syncthreads();

    int tx = t & 15, ty = t >> 4;
    float acc[8][8];
#pragma unroll
    for (int r = 0; r < 8; r++)
#pragma unroll
        for (int c = 0; c < 8; c++) acc[r][c] = 0.f;

#pragma unroll 4
    for (int d = 0; d < 64; d++) {
        float a[8], b[8];
#pragma unroll
        for (int r = 0; r < 8; r++) a[r] = sA[d * SC_PITCH + ty * 8 + r];
#pragma unroll
        for (int c = 0; c < 8; c++) b[c] = sB[d * SC_PITCH + tx * 8 + c];
#pragma unroll
        for (int r = 0; r < 8; r++)
#pragma unroll
            for (int c = 0; c < 8; c++) acc[r][c] = fmaf(a[r], b[c], acc[r][c]);
    }

    float ni[8], nj[8], qj[8];
#pragma unroll
    for (int r = 0; r < 8; r++) ni[r] = g_norm[i0 + ty * 8 + r];
#pragma unroll
    for (int c = 0; c < 8; c++) {
        nj[c] = g_norm[j0 + tx * 8 + c];
        qj[c] = qual[j0 + tx * 8 + c];
    }
#pragma unroll
    for (int r = 0; r < 8; r++) {
        float s[8];
#pragma unroll
        for (int c = 0; c < 8; c++) {
            float d2 = ni[r] + nj[c] - 2.f * acc[r][c];
            s[c] = -sqrtf(fmaxf(d2, 0.f)) + qj[c];
        }
        float* dst = g_S + (size_t)(i0 + ty * 8 + r) * N_TOK + j0 + tx * 8;
        reinterpret_cast<float4*>(dst)[0] = make_float4(s[0], s[1], s[2], s[3]);
        reinterpret_cast<float4*>(dst)[1] = make_float4(s[4], s[5], s[6], s[7]);
    }
}

// ---------------- K4: row softmax + bf16 hi/lo split -----------------------
__global__ __launch_bounds__(256) void k_softmax() {
    __shared__ float red[256];
    int i = blockIdx.x, t = threadIdx.x;
    const float4* row = reinterpret_cast<const float4*>(g_S + (size_t)i * N_TOK);
    float4 v[8];
    float m = -1e30f;
#pragma unroll
    for (int k = 0; k < 8; k++) {
        v[k] = row[k * 256 + t];
        m = fmaxf(m, fmaxf(fmaxf(v[k].x, v[k].y), fmaxf(v[k].z, v[k].w)));
    }
    red[t] = m;
    __syncthreads();
    for (int s = 128; s > 0; s >>= 1) {
        if (t < s) red[t] = fmaxf(red[t], red[t + s]);
        __syncthreads();
    }
    m = red[0];
    __syncthreads();

    float sum = 0.f;
#pragma unroll
    for (int k = 0; k < 8; k++) {
        v[k].x = __expf(v[k].x - m);
        v[k].y = __expf(v[k].y - m);
        v[k].z = __expf(v[k].z - m);
        v[k].w = __expf(v[k].w - m);
        sum += v[k].x + v[k].y + v[k].z + v[k].w;
    }
    red[t] = sum;
    __syncthreads();
    for (int s = 128; s > 0; s >>= 1) {
        if (t < s) red[t] += red[t + s];
        __syncthreads();
    }
    float inv = 1.f / red[0];

#pragma unroll
    for (int k = 0; k < 8; k++) {
        float p0 = v[k].x * inv, p1 = v[k].y * inv, p2 = v[k].z * inv, p3 = v[k].w * inv;
        __nv_bfloat16 h0 = __float2bfloat16(p0), h1 = __float2bfloat16(p1);
        __nv_bfloat16 h2 = __float2bfloat16(p2), h3 = __float2bfloat16(p3);
        __nv_bfloat16 l0 = __float2bfloat16(p0 - __bfloat162float(h0));
        __nv_bfloat16 l1 = __float2bfloat16(p1 - __bfloat162float(h1));
        __nv_bfloat16 l2 = __float2bfloat16(p2 - __bfloat162float(h2));
        __nv_bfloat16 l3 = __float2bfloat16(p3 - __bfloat162float(h3));
        size_t base = (size_t)i * N_TOK + (size_t)(k * 256 + t) * 4;
        __nv_bfloat162 hp01; hp01.x = h0; hp01.y = h1;
        __nv_bfloat162 hp23; hp23.x = h2; hp23.y = h3;
        __nv_bfloat162 lp01; lp01.x = l0; lp01.y = l1;
        __nv_bfloat162 lp23; lp23.x = l2; lp23.y = l3;
        reinterpret_cast<__nv_bfloat162*>(g_Phi + base)[0] = hp01;
        reinterpret_cast<__nv_bfloat162*>(g_Phi + base)[1] = hp23;
        reinterpret_cast<__nv_bfloat162*>(g_Plo + base)[0] = lp01;
        reinterpret_cast<__nv_bfloat162*>(g_Plo + base)[1] = lp23;
    }
}

// ---------------- K5: HMMA GEMM  out = P @ E  (split bf16, fp32 acc) -------
// CTA tile M=256 x N=128, BK=32, 512 threads (16 warps, 4x4, warp tile 64x32)
// 3 products per chunk: Phi*Ehi + Phi*Elo + Plo*Ehi  (lo*lo dropped, ~1e-5)
#define BM 256
#define BN 128
#define BK 32
#define STAGES 3
#define NCHUNK (N_TOK / BK)   // 256

static constexpr int A_BYTES     = BM * 64;                  // 16384 (one matrix)
static constexpr int B_BYTES     = BN * 64;                  //  8192
static constexpr int OFF_AHI     = 0;
static constexpr int OFF_ALO     = A_BYTES;
static constexpr int OFF_BHI     = 2 * A_BYTES;
static constexpr int OFF_BLO     = 2 * A_BYTES + B_BYTES;
static constexpr int STAGE_BYTES = 2 * A_BYTES + 2 * B_BYTES; // 49152
static constexpr int GEMM_SMEM   = STAGES * STAGE_BYTES;      // 147456

// swizzled smem offset for a 16B segment: rows are 64B (4 segs)
__device__ __forceinline__ uint32_t swz(int row, int seg) {
    return (uint32_t)(row * 64 + ((seg ^ ((row >> 1) & 3)) << 4));
}

__device__ __forceinline__ void issue_chunk(uint32_t sbase, int m0, int g0, int k0, int t) {
    // 3072 16B segments: Ahi 1024 | Alo 1024 | Bhi 512 | Blo 512
#pragma unroll
    for (int it = 0; it < 6; it++) {
        int x = t + it * 512;
        const __nv_bfloat16* src;
        uint32_t dstb;
        int row, seg, grow;
        if (x < 1024)       { row = x >> 2;          seg = x & 3; src = g_Phi;  dstb = sbase + OFF_AHI; grow = m0 + row; }
        else if (x < 2048)  { int y = x - 1024; row = y >> 2; seg = y & 3; src = g_Plo;  dstb = sbase + OFF_ALO; grow = m0 + row; }
        else if (x < 2560)  { int y = x - 2048; row = y >> 2; seg = y & 3; src = g_EhiT; dstb = sbase + OFF_BHI; grow = g0 + row; }
        else                { int y = x - 2560; row = y >> 2; seg = y & 3; src = g_EloT; dstb = sbase + OFF_BLO; grow = g0 + row; }
        cp16(dstb + swz(row, seg), src + (size_t)grow * N_TOK + k0 + seg * 8);
    }
    CP_COMMIT();
}

__global__ __launch_bounds__(512, 1) void k_gemm(float* __restrict__ out) {
    extern __shared__ char dyn_smem[];
    uint32_t smem_base = smem_u32(dyn_smem);
    int t = threadIdx.x;
    int wid = t >> 5, lane = t & 31;
    int wm = wid & 3, wn = wid >> 2;          // 4x4 warps
    int g0 = blockIdx.x * BN;
    int m0 = blockIdx.y * BM;

    float acc[4][4][4];
#pragma unroll
    for (int a = 0; a < 4; a++)
#pragma unroll
        for (int b = 0; b < 4; b++)
#pragma unroll
            for (int c = 0; c < 4; c++) acc[a][b][c] = 0.f;

    // prologue: stages 0,1
    issue_chunk(smem_base + 0 * STAGE_BYTES, m0, g0, 0 * BK, t);
    issue_chunk(smem_base + 1 * STAGE_BYTES, m0, g0, 1 * BK, t);

    // ldmatrix lane address components (row/seg patterns)
    int aRow = (lane & 15);                 // + mtile*16 + wm*64
    int aSegL = (lane >> 4);                // + kk/8
    int bRow = (lane & 7) + ((lane >> 4) << 3);   // + ntile2*16 + wn*32
    int bSegL = ((lane >> 3) & 1);          // + kk/8

    for (int kc = 0; kc < NCHUNK; kc++) {
        CP_WAIT(1);
        __syncthreads();
        if (kc + 2 < NCHUNK)
            issue_chunk(smem_base + ((kc + 2) % STAGES) * STAGE_BYTES, m0, g0, (kc + 2) * BK, t);

        uint32_t sb = smem_base + (kc % STAGES) * STAGE_BYTES;
        uint32_t sAhi = sb + OFF_AHI, sAlo = sb + OFF_ALO;
        uint32_t sBhi = sb + OFF_BHI, sBlo = sb + OFF_BLO;

#pragma unroll
        for (int kk = 0; kk < 2; kk++) {     // two k16 steps
            int ks = kk * 2;                 // seg base (kk*16 elems = 32B)
            uint32_t aHi[4][4], aLo[4][4], bF[2][4];
#pragma unroll
            for (int mt = 0; mt < 4; mt++) {
                int row = wm * 64 + mt * 16 + aRow;
                ldsm4(aHi[mt], sAhi + swz(row, ks + aSegL));
            }
#pragma unroll
            for (int nt = 0; nt < 2; nt++) {
                int row = wn * 32 + nt * 16 + bRow;
                ldsm4(bF[nt], sBhi + swz(row, ks + bSegL));
            }
            // Phi * Ehi
#pragma unroll
            for (int mt = 0; mt < 4; mt++)
#pragma unroll
                for (int n8 = 0; n8 < 4; n8++)
                    mma16816(acc[mt][n8], aHi[mt], &bF[n8 >> 1][(n8 & 1) * 2]);
            // Plo * Ehi
#pragma unroll
            for (int mt = 0; mt < 4; mt++) {
                int row = wm * 64 + mt * 16 + aRow;
                ldsm4(aLo[mt], sAlo + swz(row, ks + aSegL));
            }
#pragma unroll
            for (int mt = 0; mt < 4; mt++)
#pragma unroll
                for (int n8 = 0; n8 < 4; n8++)
                    mma16816(acc[mt][n8], aLo[mt], &bF[n8 >> 1][(n8 & 1) * 2]);
            // Phi * Elo
#pragma unroll
            for (int nt = 0; nt < 2; nt++) {
                int row = wn * 32 + nt * 16 + bRow;
                ldsm4(bF[nt], sBlo + swz(row, ks + bSegL));
            }
#pragma unroll
            for (int mt = 0; mt < 4; mt++)
#pragma unroll
                for (int n8 = 0; n8 < 4; n8++)
                    mma16816(acc[mt][n8], aHi[mt], &bF[n8 >> 1][(n8 & 1) * 2]);
        }
        __syncthreads();
    }

    // epilogue: direct fp32 stores (float2 per mma C-frag half)
    int rbase = m0 + wm * 64 + (lane >> 2);
    int cbase = g0 + wn * 32 + 2 * (lane & 3);
#pragma unroll
    for (int mt = 0; mt < 4; mt++) {
#pragma unroll
        for (int n8 = 0; n8 < 4; n8++) {
            int r = rbase + mt * 16;
            int c = cbase + n8 * 8;
            float2 v0 = make_float2(acc[mt][n8][0], acc[mt][n8][1]);
            float2 v1 = make_float2(acc[mt][n8][2], acc[mt][n8][3]);
            *reinterpret_cast<float2*>(out + (size_t)r * G_DIM + c) = v0;
            *reinterpret_cast<float2*>(out + (size_t)(r + 8) * G_DIM + c) = v1;
        }
    }
}

// ---------------- launch ---------------------------------------------------
extern "C" void kernel_launch(void* const* d_in, const int* in_sizes, int n_in,
                              void* d_out, int out_size) {
    const float* expression = (const float*)d_in[0];   // [8192, 2048]
    const float* encoding   = (const float*)d_in[1];   // [8192, 64]
    const float* quality    = (const float*)d_in[2];   // [8192]
    float* out = (float*)d_out;                        // [8192, 2048]

    cudaFuncSetAttribute(k_score, cudaFuncAttributeMaxDynamicSharedMemorySize,
                         2 * 64 * SC_PITCH * 4);
    cudaFuncSetAttribute(k_gemm, cudaFuncAttributeMaxDynamicSharedMemorySize, GEMM_SMEM);

    k_norm<<<N_TOK / 256, 256>>>(encoding);
    k_esplit<<<dim3(G_DIM / 32, N_TOK / 32), dim3(32, 8)>>>(expression);
    k_score<<<dim3(N_TOK / 128, N_TOK / 128), 256, 2 * 64 * SC_PITCH * 4>>>(encoding, quality);
    k_softmax<<<N_TOK, 256>>>();
    k_gemm<<<dim3(G_DIM / BN, N_TOK / BM), 512, GEMM_SMEM>>>(out);
}

// round 8
// speedup vs baseline: 1.0540x; 1.0540x over previous
#include <cuda_runtime.h>
#include <cuda_bf16.h>
#include <cstdint>
#include <cstddef>

#define N_TOK 8192
#define G_DIM 2048
#define D_DIM 64

// ---------------- scratch (static device allocations are allowed) ----------
__device__ float         g_S    [(size_t)N_TOK * N_TOK];   // 256 MB scores
__device__ __nv_bfloat16 g_Phi  [(size_t)N_TOK * N_TOK];   // 128 MB
__device__ __nv_bfloat16 g_Plo  [(size_t)N_TOK * N_TOK];   // 128 MB
__device__ __nv_bfloat16 g_EhiT [(size_t)G_DIM * N_TOK];   //  32 MB (transposed)
__device__ __nv_bfloat16 g_EloT [(size_t)G_DIM * N_TOK];   //  32 MB
__device__ __nv_bfloat16 g_enchi[(size_t)N_TOK * D_DIM];   //   1 MB
__device__ __nv_bfloat16 g_enclo[(size_t)N_TOK * D_DIM];   //   1 MB
__device__ float         g_norm [N_TOK];

// ---------------- PTX helpers ----------------------------------------------
__device__ __forceinline__ uint32_t smem_u32(const void* p) {
    uint32_t r;
    asm("{ .reg .u64 t; cvta.to.shared.u64 t, %1; cvt.u32.u64 %0, t; }"
        : "=r"(r) : "l"(p));
    return r;
}

__device__ __forceinline__ void cp16(uint32_t dst, const void* src) {
    asm volatile("cp.async.cg.shared.global [%0], [%1], 16;" :: "r"(dst), "l"(src));
}
#define CP_COMMIT() asm volatile("cp.async.commit_group;" ::: "memory")
#define CP_WAIT(n)  asm volatile("cp.async.wait_group %0;" :: "n"(n) : "memory")

__device__ __forceinline__ void ldsm4(uint32_t* r, uint32_t addr) {
    asm volatile("ldmatrix.sync.aligned.m8n8.x4.shared.b16 {%0,%1,%2,%3}, [%4];"
                 : "=r"(r[0]), "=r"(r[1]), "=r"(r[2]), "=r"(r[3]) : "r"(addr));
}

__device__ __forceinline__ void mma16816(float* c, const uint32_t* a, const uint32_t* b) {
    asm volatile(
        "mma.sync.aligned.m16n8k16.row.col.f32.bf16.bf16.f32 "
        "{%0,%1,%2,%3}, {%4,%5,%6,%7}, {%8,%9}, {%0,%1,%2,%3};"
        : "+f"(c[0]), "+f"(c[1]), "+f"(c[2]), "+f"(c[3])
        : "r"(a[0]), "r"(a[1]), "r"(a[2]), "r"(a[3]), "r"(b[0]), "r"(b[1]));
}

// ---------------- K1: fused prep -------------------------------------------
// blocks [0, 16384): transpose+split expression -> E_hi^T/E_lo^T [2048,8192]
// blocks [16384, 16416): split encoding rows into bf16 hi/lo + fp32 norms
__global__ __launch_bounds__(256) void k_prep(const float* __restrict__ expr,
                                              const float* __restrict__ enc) {
    int b = blockIdx.x, t = threadIdx.x;
    if (b < 16384) {
        __shared__ float tile[32][33];
        int g0 = (b & 63) * 32, j0 = (b >> 6) * 32;
        int tx = t & 31, ty = t >> 5;       // 32 x 8
#pragma unroll
        for (int i = 0; i < 32; i += 8)
            tile[ty + i][tx] = expr[(size_t)(j0 + ty + i) * G_DIM + g0 + tx];
        __syncthreads();
#pragma unroll
        for (int i = 0; i < 32; i += 8) {
            int g = g0 + ty + i, j = j0 + tx;
            float v = tile[tx][ty + i];
            __nv_bfloat16 h = __float2bfloat16(v);
            float r = v - __bfloat162float(h);
            g_EhiT[(size_t)g * N_TOK + j] = h;
            g_EloT[(size_t)g * N_TOK + j] = __float2bfloat16(r);
        }
    } else {
        int row = (b - 16384) * 256 + t;    // one encoding row per thread
        const float4* p = reinterpret_cast<const float4*>(enc + (size_t)row * D_DIM);
        float s = 0.f;
        __nv_bfloat162* oh = reinterpret_cast<__nv_bfloat162*>(g_enchi + (size_t)row * D_DIM);
        __nv_bfloat162* ol = reinterpret_cast<__nv_bfloat162*>(g_enclo + (size_t)row * D_DIM);
#pragma unroll
        for (int k = 0; k < 16; k++) {
            float4 v = p[k];
            s += v.x * v.x + v.y * v.y + v.z * v.z + v.w * v.w;
            float f[4] = {v.x, v.y, v.z, v.w};
            __nv_bfloat16 h[4], l[4];
#pragma unroll
            for (int q = 0; q < 4; q++) {
                h[q] = __float2bfloat16(f[q]);
                l[q] = __float2bfloat16(f[q] - __bfloat162float(h[q]));
            }
            __nv_bfloat162 h01; h01.x = h[0]; h01.y = h[1];
            __nv_bfloat162 h23; h23.x = h[2]; h23.y = h[3];
            __nv_bfloat162 l01; l01.x = l[0]; l01.y = l[1];
            __nv_bfloat162 l23; l23.x = l[2]; l23.y = l[3];
            oh[k * 2 + 0] = h01; oh[k * 2 + 1] = h23;
            ol[k * 2 + 0] = l01; ol[k * 2 + 1] = l23;
        }
        g_norm[row] = s;
    }
}

// ---------------- K2: HMMA score matrix S = -dist + q_j --------------------
// CTA tile 128x128, 8 warps (4m x 2n), warp tile 32x64, K=64 (4 k16 steps).
// 3-term split: Ihi*Jhi + Ilo*Jhi + Ihi*Jlo ; diagonal forced to exact 0.
static constexpr int SC_MAT   = 128 * 128;          // 16 KB per bf16 matrix tile
static constexpr int SC_SMEM  = 4 * SC_MAT + 3 * 128 * 4;  // 67072

__device__ __forceinline__ uint32_t swz128(int row, int seg) {
    return (uint32_t)(row * 128 + ((seg ^ (row & 7)) << 4));
}

__global__ __launch_bounds__(256) void k_score(const float* __restrict__ qual) {
    extern __shared__ char dyn_smem[];
    uint32_t sbase = smem_u32(dyn_smem);
    float* ni = reinterpret_cast<float*>(dyn_smem + 4 * SC_MAT);
    float* nj = ni + 128;
    float* qj = nj + 128;
    int t = threadIdx.x, wid = t >> 5, lane = t & 31;
    int wm = wid & 3, wn = wid >> 2;
    int j0 = blockIdx.x * 128, i0 = blockIdx.y * 128;

    if (t < 128) ni[t] = g_norm[i0 + t];
    else { nj[t - 128] = g_norm[j0 + t - 128]; qj[t - 128] = qual[j0 + t - 128]; }

    // load 4 matrices: Ihi | Ilo | Jhi | Jlo (128 rows x 64 bf16 = 128B/row)
#pragma unroll
    for (int it = 0; it < 16; it++) {
        int x = t + it * 256;
        int mat = x >> 10, y = x & 1023, row = y >> 3, seg = y & 7;
        const __nv_bfloat16* src = (mat == 0) ? g_enchi : (mat == 1) ? g_enclo
                                 : (mat == 2) ? g_enchi : g_enclo;
        int grow = ((mat < 2) ? i0 : j0) + row;
        cp16(sbase + mat * SC_MAT + swz128(row, seg),
             src + (size_t)grow * D_DIM + seg * 8);
    }
    CP_COMMIT();

    float acc[2][8][4];
#pragma unroll
    for (int a = 0; a < 2; a++)
#pragma unroll
        for (int b = 0; b < 8; b++)
#pragma unroll
            for (int c = 0; c < 4; c++) acc[a][b][c] = 0.f;

    CP_WAIT(0);
    __syncthreads();

    uint32_t sIhi = sbase, sIlo = sbase + SC_MAT;
    uint32_t sJhi = sbase + 2 * SC_MAT, sJlo = sbase + 3 * SC_MAT;
    int aRow = lane & 15, aSegL = lane >> 4;
    int bRow = (lane & 7) + ((lane >> 4) << 3), bSegL = (lane >> 3) & 1;

#pragma unroll
    for (int kk = 0; kk < 4; kk++) {
        int ks = kk * 2;
        uint32_t aHi[2][4], aLo[2][4], bHi[4][4], bLo[4][4];
#pragma unroll
        for (int mt = 0; mt < 2; mt++) {
            int row = wm * 32 + mt * 16 + aRow;
            ldsm4(aHi[mt], sIhi + swz128(row, ks + aSegL));
            ldsm4(aLo[mt], sIlo + swz128(row, ks + aSegL));
        }
#pragma unroll
        for (int nt = 0; nt < 4; nt++) {
            int row = wn * 64 + nt * 16 + bRow;
            ldsm4(bHi[nt], sJhi + swz128(row, ks + bSegL));
            ldsm4(bLo[nt], sJlo + swz128(row, ks + bSegL));
        }
#pragma unroll
        for (int mt = 0; mt < 2; mt++)
#pragma unroll
            for (int n8 = 0; n8 < 8; n8++) {
                mma16816(acc[mt][n8], aHi[mt], &bHi[n8 >> 1][(n8 & 1) * 2]);
                mma16816(acc[mt][n8], aLo[mt], &bHi[n8 >> 1][(n8 & 1) * 2]);
                mma16816(acc[mt][n8], aHi[mt], &bLo[n8 >> 1][(n8 & 1) * 2]);
            }
    }

    // epilogue: d2 = ni + nj - 2*dot ; s = -sqrt(max(d2,0)) + qj ; diag -> qj
#pragma unroll
    for (int mt = 0; mt < 2; mt++) {
#pragma unroll
        for (int n8 = 0; n8 < 8; n8++) {
            int ri = wm * 32 + mt * 16 + (lane >> 2);
            int cj = wn * 64 + n8 * 8 + (lane & 3) * 2;
#pragma unroll
            for (int half = 0; half < 2; half++) {
                int r = ri + half * 8;
                float nr = ni[r];
                float s0, s1;
                {
                    float d2 = nr + nj[cj] - 2.f * acc[mt][n8][half * 2 + 0];
                    s0 = -sqrtf(fmaxf(d2, 0.f)) + qj[cj];
                    if (i0 + r == j0 + cj) s0 = qj[cj];
                }
                {
                    float d2 = nr + nj[cj + 1] - 2.f * acc[mt][n8][half * 2 + 1];
                    s1 = -sqrtf(fmaxf(d2, 0.f)) + qj[cj + 1];
                    if (i0 + r == j0 + cj + 1) s1 = qj[cj + 1];
                }
                *reinterpret_cast<float2*>(g_S + (size_t)(i0 + r) * N_TOK + j0 + cj)
                    = make_float2(s0, s1);
            }
        }
    }
}

// ---------------- K3: row softmax + bf16 hi/lo split -----------------------
__global__ __launch_bounds__(256) void k_softmax() {
    __shared__ float red[256];
    int i = blockIdx.x, t = threadIdx.x;
    const float4* row = reinterpret_cast<const float4*>(g_S + (size_t)i * N_TOK);
    float4 v[8];
    float m = -1e30f;
#pragma unroll
    for (int k = 0; k < 8; k++) {
        v[k] = row[k * 256 + t];
        m = fmaxf(m, fmaxf(fmaxf(v[k].x, v[k].y), fmaxf(v[k].z, v[k].w)));
    }
    red[t] = m;
    __syncthreads();
    for (int s = 128; s > 0; s >>= 1) {
        if (t < s) red[t] = fmaxf(red[t], red[t + s]);
        __syncthreads();
    }
    m = red[0];
    __syncthreads();

    float sum = 0.f;
#pragma unroll
    for (int k = 0; k < 8; k++) {
        v[k].x = __expf(v[k].x - m);
        v[k].y = __expf(v[k].y - m);
        v[k].z = __expf(v[k].z - m);
        v[k].w = __expf(v[k].w - m);
        sum += v[k].x + v[k].y + v[k].z + v[k].w;
    }
    red[t] = sum;
    __syncthreads();
    for (int s = 128; s > 0; s >>= 1) {
        if (t < s) red[t] += red[t + s];
        __syncthreads();
    }
    float inv = 1.f / red[0];

#pragma unroll
    for (int k = 0; k < 8; k++) {
        float p0 = v[k].x * inv, p1 = v[k].y * inv, p2 = v[k].z * inv, p3 = v[k].w * inv;
        __nv_bfloat16 h0 = __float2bfloat16(p0), h1 = __float2bfloat16(p1);
        __nv_bfloat16 h2 = __float2bfloat16(p2), h3 = __float2bfloat16(p3);
        __nv_bfloat16 l0 = __float2bfloat16(p0 - __bfloat162float(h0));
        __nv_bfloat16 l1 = __float2bfloat16(p1 - __bfloat162float(h1));
        __nv_bfloat16 l2 = __float2bfloat16(p2 - __bfloat162float(h2));
        __nv_bfloat16 l3 = __float2bfloat16(p3 - __bfloat162float(h3));
        size_t base = (size_t)i * N_TOK + (size_t)(k * 256 + t) * 4;
        __nv_bfloat162 hp01; hp01.x = h0; hp01.y = h1;
        __nv_bfloat162 hp23; hp23.x = h2; hp23.y = h3;
        __nv_bfloat162 lp01; lp01.x = l0; lp01.y = l1;
        __nv_bfloat162 lp23; lp23.x = l2; lp23.y = l3;
        reinterpret_cast<__nv_bfloat162*>(g_Phi + base)[0] = hp01;
        reinterpret_cast<__nv_bfloat162*>(g_Phi + base)[1] = hp23;
        reinterpret_cast<__nv_bfloat162*>(g_Plo + base)[0] = lp01;
        reinterpret_cast<__nv_bfloat162*>(g_Plo + base)[1] = lp23;
    }
}

// ---------------- K4: HMMA GEMM  out = P @ E  (split bf16, fp32 acc) -------
// CTA tile M=256 x N=128, BK=32, 512 threads (16 warps, 4x4, warp tile 64x32)
// 3 products: Phi*Ehi + Plo*Ehi + Phi*Elo  (lo*lo dropped)
#define BM 256
#define BN 128
#define BK 32
#define STAGES 4
#define NCHUNK (N_TOK / BK)   // 256

static constexpr int A_BYTES     = BM * 64;                  // 16384 (one matrix)
static constexpr int B_BYTES     = BN * 64;                  //  8192
static constexpr int OFF_AHI     = 0;
static constexpr int OFF_ALO     = A_BYTES;
static constexpr int OFF_BHI     = 2 * A_BYTES;
static constexpr int OFF_BLO     = 2 * A_BYTES + B_BYTES;
static constexpr int STAGE_BYTES = 2 * A_BYTES + 2 * B_BYTES; // 49152
static constexpr int GEMM_SMEM   = STAGES * STAGE_BYTES;      // 196608

// swizzled smem offset for a 16B segment: rows are 64B (4 segs)
__device__ __forceinline__ uint32_t swz(int row, int seg) {
    return (uint32_t)(row * 64 + ((seg ^ ((row >> 1) & 3)) << 4));
}

__device__ __forceinline__ void issue_chunk(uint32_t sbase, int m0, int g0, int k0, int t) {
#pragma unroll
    for (int it = 0; it < 6; it++) {
        int x = t + it * 512;
        const __nv_bfloat16* src;
        uint32_t dstb;
        int row, seg, grow;
        if (x < 1024)       { row = x >> 2;          seg = x & 3; src = g_Phi;  dstb = sbase + OFF_AHI; grow = m0 + row; }
        else if (x < 2048)  { int y = x - 1024; row = y >> 2; seg = y & 3; src = g_Plo;  dstb = sbase + OFF_ALO; grow = m0 + row; }
        else if (x < 2560)  { int y = x - 2048; row = y >> 2; seg = y & 3; src = g_EhiT; dstb = sbase + OFF_BHI; grow = g0 + row; }
        else                { int y = x - 2560; row = y >> 2; seg = y & 3; src = g_EloT; dstb = sbase + OFF_BLO; grow = g0 + row; }
        cp16(dstb + swz(row, seg), src + (size_t)grow * N_TOK + k0 + seg * 8);
    }
    CP_COMMIT();
}

__global__ __launch_bounds__(512, 1) void k_gemm(float* __restrict__ out) {
    extern __shared__ char dyn_smem[];
    uint32_t smem_base = smem_u32(dyn_smem);
    int t = threadIdx.x;
    int wid = t >> 5, lane = t & 31;
    int wm = wid & 3, wn = wid >> 2;          // 4x4 warps
    int g0 = blockIdx.x * BN;
    int m0 = blockIdx.y * BM;

    float acc[4][4][4];
#pragma unroll
    for (int a = 0; a < 4; a++)
#pragma unroll
        for (int b = 0; b < 4; b++)
#pragma unroll
            for (int c = 0; c < 4; c++) acc[a][b][c] = 0.f;

    // prologue: stages 0,1,2
    issue_chunk(smem_base + 0 * STAGE_BYTES, m0, g0, 0 * BK, t);
    issue_chunk(smem_base + 1 * STAGE_BYTES, m0, g0, 1 * BK, t);
    issue_chunk(smem_base + 2 * STAGE_BYTES, m0, g0, 2 * BK, t);

    int aRow = (lane & 15);
    int aSegL = (lane >> 4);
    int bRow = (lane & 7) + ((lane >> 4) << 3);
    int bSegL = ((lane >> 3) & 1);

    for (int kc = 0; kc < NCHUNK; kc++) {
        CP_WAIT(2);            // oldest in-flight group (kc) complete
        __syncthreads();       // also protects buffer (kc+3)%4 from overwrite
        if (kc + 3 < NCHUNK)
            issue_chunk(smem_base + ((kc + 3) % STAGES) * STAGE_BYTES, m0, g0, (kc + 3) * BK, t);

        uint32_t sb = smem_base + (kc % STAGES) * STAGE_BYTES;
        uint32_t sAhi = sb + OFF_AHI, sAlo = sb + OFF_ALO;
        uint32_t sBhi = sb + OFF_BHI, sBlo = sb + OFF_BLO;

#pragma unroll
        for (int kk = 0; kk < 2; kk++) {     // two k16 steps
            int ks = kk * 2;
            uint32_t aHi[4][4], aLo[4][4], bF[2][4];
#pragma unroll
            for (int mt = 0; mt < 4; mt++) {
                int row = wm * 64 + mt * 16 + aRow;
                ldsm4(aHi[mt], sAhi + swz(row, ks + aSegL));
            }
#pragma unroll
            for (int nt = 0; nt < 2; nt++) {
                int row = wn * 32 + nt * 16 + bRow;
                ldsm4(bF[nt], sBhi + swz(row, ks + bSegL));
            }
            // Phi * Ehi
#pragma unroll
            for (int mt = 0; mt < 4; mt++)
#pragma unroll
                for (int n8 = 0; n8 < 4; n8++)
                    mma16816(acc[mt][n8], aHi[mt], &bF[n8 >> 1][(n8 & 1) * 2]);
            // Plo * Ehi
#pragma unroll
            for (int mt = 0; mt < 4; mt++) {
                int row = wm * 64 + mt * 16 + aRow;
                ldsm4(aLo[mt], sAlo + swz(row, ks + aSegL));
            }
#pragma unroll
            for (int mt = 0; mt < 4; mt++)
#pragma unroll
                for (int n8 = 0; n8 < 4; n8++)
                    mma16816(acc[mt][n8], aLo[mt], &bF[n8 >> 1][(n8 & 1) * 2]);
            // Phi * Elo
#pragma unroll
            for (int nt = 0; nt < 2; nt++) {
                int row = wn * 32 + nt * 16 + bRow;
                ldsm4(bF[nt], sBlo + swz(row, ks + bSegL));
            }
#pragma unroll
            for (int mt = 0; mt < 4; mt++)
#pragma unroll
                for (int n8 = 0; n8 < 4; n8++)
                    mma16816(acc[mt][n8], aHi[mt], &bF[n8 >> 1][(n8 & 1) * 2]);
        }
    }

    // epilogue: direct fp32 stores
    int rbase = m0 + wm * 64 + (lane >> 2);
    int cbase = g0 + wn * 32 + 2 * (lane & 3);
#pragma unroll
    for (int mt = 0; mt < 4; mt++) {
#pragma unroll
        for (int n8 = 0; n8 < 4; n8++) {
            int r = rbase + mt * 16;
            int c = cbase + n8 * 8;
            float2 v0 = make_float2(acc[mt][n8][0], acc[mt][n8][1]);
            float2 v1 = make_float2(acc[mt][n8][2], acc[mt][n8][3]);
            *reinterpret_cast<float2*>(out + (size_t)r * G_DIM + c) = v0;
            *reinterpret_cast<float2*>(out + (size_t)(r + 8) * G_DIM + c) = v1;
        }
    }
}

// ---------------- launch ---------------------------------------------------
extern "C" void kernel_launch(void* const* d_in, const int* in_sizes, int n_in,
                              void* d_out, int out_size) {
    const float* expression = (const float*)d_in[0];   // [8192, 2048]
    const float* encoding   = (const float*)d_in[1];   // [8192, 64]
    const float* quality    = (const float*)d_in[2];   // [8192]
    float* out = (float*)d_out;                        // [8192, 2048]

    cudaFuncSetAttribute(k_score, cudaFuncAttributeMaxDynamicSharedMemorySize, SC_SMEM);
    cudaFuncSetAttribute(k_gemm, cudaFuncAttributeMaxDynamicSharedMemorySize, GEMM_SMEM);

    k_prep<<<16384 + 32, 256>>>(expression, encoding);
    k_score<<<dim3(N_TOK / 128, N_TOK / 128), 256, SC_SMEM>>>(quality);
    k_softmax<<<N_TOK, 256>>>();
    k_gemm<<<dim3(G_DIM / BN, N_TOK / BM), 512, GEMM_SMEM>>>(out);
}